// round 13
// baseline (speedup 1.0000x reference)
#include <cuda_runtime.h>
#include <cuda_bf16.h>
#include <math.h>
#include <stdint.h>

// ---------------- problem constants ----------------
#define Bc    8
#define NAc   4096
#define NAAc  1024
#define NPCc  4096
#define Kc    16
#define KNCc  14
#define Gc    32
#define DAc   12
#define Fc    128
#define Dc    128
#define NATOM (Bc*NAc)      // 32768
#define NAAT  (Bc*NAAc)     // 8192
#define MDIM  (Gc*DAc)      // 384

// ---------------- scratch (device globals; no allocations allowed) ----------------
__device__ float g_center[NATOM*3];
__device__ float g_amat[NATOM*DAc];
__device__ float g_masky[NATOM];
__device__ float g_M[(size_t)NATOM*MDIM];            // 48 MB
__device__ __nv_bfloat16 g_Wch[2*Dc*Fc];             // Wcat^T hi [256 n][128 k]
__device__ __nv_bfloat16 g_Wcl[2*Dc*Fc];
__device__ float g_af[(size_t)NATOM*2*Dc];           // 32 MB (att | feat)
__device__ float g_pooled[(size_t)NAAT*Dc];
__device__ float g_part[64*3*Dc];                    // k5 partials
__device__ float g_mean[Dc];
__device__ float g_inv[Dc];

// ---------------- helpers ----------------
__device__ __forceinline__ void split2(float f0, float f1, uint32_t& hi, uint32_t& lo)
{
    __nv_bfloat16 h0 = __float2bfloat16_rn(f0);
    __nv_bfloat16 h1 = __float2bfloat16_rn(f1);
    __nv_bfloat16 l0 = __float2bfloat16_rn(f0 - __bfloat162float(h0));
    __nv_bfloat16 l1 = __float2bfloat16_rn(f1 - __bfloat162float(h1));
    hi = ((uint32_t)__bfloat16_as_ushort(h1) << 16) | (uint32_t)__bfloat16_as_ushort(h0);
    lo = ((uint32_t)__bfloat16_as_ushort(l1) << 16) | (uint32_t)__bfloat16_as_ushort(l0);
}
__device__ __forceinline__ void mma_bf16(float* d, const uint32_t* a, const uint32_t* b)
{
    asm("mma.sync.aligned.m16n8k16.row.col.f32.bf16.bf16.f32 "
        "{%0,%1,%2,%3},{%4,%5,%6,%7},{%8,%9},{%0,%1,%2,%3};"
        : "+f"(d[0]), "+f"(d[1]), "+f"(d[2]), "+f"(d[3])
        : "r"(a[0]), "r"(a[1]), "r"(a[2]), "r"(a[3]), "r"(b[0]), "r"(b[1]));
}
#define FMA2(d, a, b) \
    asm("fma.rn.f32x2 %0, %1, %2, %3;" : "+l"(d) : "l"(a), "l"(b), "l"(d))

// ---------------- K0w: per-atom prep + Wcat transpose/split (merged) ----------------
__global__ void k0w(const float* __restrict__ pc,
                    const float* __restrict__ mask_atom,
                    const float* __restrict__ attr_table,
                    const int*  __restrict__ frame_idx,
                    const int*  __restrict__ attr_idx,
                    const float* __restrict__ Watt,
                    const float* __restrict__ Wfeat)
{
    int idx = blockIdx.x * blockDim.x + threadIdx.x;
    if (idx < NATOM) {
        int t = idx;
        int b = t / NAc;
        int f1 = frame_idx[t*3 + 1];
        const float* p = pc + ((size_t)b*NPCc + f1)*3;
        g_center[t*3+0] = p[0];
        g_center[t*3+1] = p[1];
        g_center[t*3+2] = p[2];

        int ai = attr_idx[t];
        const float* arow = attr_table + (size_t)ai*DAc;
        float av[DAc];
        bool nz = false;
#pragma unroll
        for (int a = 0; a < DAc; a++) { av[a] = arow[a]; nz = nz || (av[a] != 0.0f); }
        float mattr = nz ? 1.0f : 0.0f;
#pragma unroll
        for (int a = 0; a < DAc; a++) g_amat[(size_t)t*DAc + a] = av[a]*mattr;
        g_masky[t] = mask_atom[t]*mattr;
    } else if (idx < NATOM + 2*Dc*Fc) {
        int j = idx - NATOM;
        int n = j >> 7, k = j & 127;
        float f = (n < Dc) ? Watt[(size_t)k*Dc + n] : Wfeat[(size_t)k*Dc + (n - Dc)];
        __nv_bfloat16 h = __float2bfloat16_rn(f);
        g_Wch[j] = h;
        g_Wcl[j] = __float2bfloat16_rn(f - __bfloat162float(h));
    }
}

// ---------------- K1: per-atom M build (warp per atom, lane = gaussian) ----------------
__global__ void k1_buildM(const float* __restrict__ pc,
                          const int*  __restrict__ frame_idx,
                          const int*  __restrict__ nb_idx,
                          const float* __restrict__ gauss)
{
    int warp = (blockIdx.x * blockDim.x + threadIdx.x) >> 5;
    int lane = threadIdx.x & 31;
    if (warp >= NATOM) return;
    int b = warp / NAc;
    const float* pcb = pc + (size_t)b*NPCc*3;

    int f0 = frame_idx[warp*3+0];
    int f1 = frame_idx[warp*3+1];
    int f2 = frame_idx[warp*3+2];

    float cx = pcb[f1*3+0], cy = pcb[f1*3+1], cz = pcb[f1*3+2];

    float u1x = pcb[f2*3+0]-cx, u1y = pcb[f2*3+1]-cy, u1z = pcb[f2*3+2]-cz;
    float inv = 1.0f/(sqrtf(u1x*u1x+u1y*u1y+u1z*u1z)+1e-8f);
    u1x*=inv; u1y*=inv; u1z*=inv;

    float vx = pcb[f0*3+0]-cx, vy = pcb[f0*3+1]-cy, vz = pcb[f0*3+2]-cz;
    float dt = vx*u1x+vy*u1y+vz*u1z;
    float u2x = vx-dt*u1x, u2y = vy-dt*u1y, u2z = vz-dt*u1z;
    inv = 1.0f/(sqrtf(u2x*u2x+u2y*u2y+u2z*u2z)+1e-8f);
    u2x*=inv; u2y*=inv; u2z*=inv;

    float u3x = u1y*u2z-u1z*u2y;
    float u3y = u1z*u2x-u1x*u2z;
    float u3z = u1x*u2y-u1y*u2x;

    int nbg_l = 0;
    float r1 = 0.0f, r2 = 0.0f, r3 = 0.0f;
    if (lane < Kc) {
        nbg_l = b*NAc + nb_idx[(size_t)warp*Kc + lane];
        float dx = g_center[nbg_l*3+0]-cx;
        float dy = g_center[nbg_l*3+1]-cy;
        float dz = g_center[nbg_l*3+2]-cz;
        r1 = u1x*dx+u1y*dy+u1z*dz;
        r2 = u2x*dx+u2y*dy+u2z*dz;
        r3 = u3x*dx+u3y*dy+u3z*dz;
    }

    float gcx = gauss[lane*3+0], gcy = gauss[lane*3+1], gcz = gauss[lane*3+2];

    unsigned long long acc2[6];
#pragma unroll
    for (int p = 0; p < 6; p++) acc2[p] = 0ull;

    const float NHL2E = -0.72134752044448170368f;   // -0.5 * log2(e)

#pragma unroll
    for (int k = 0; k < Kc; k++) {
        int   nbg = __shfl_sync(0xffffffffu, nbg_l, k);
        float t1  = __shfl_sync(0xffffffffu, r1, k) - gcx;
        float t2  = __shfl_sync(0xffffffffu, r2, k) - gcy;
        float t3  = __shfl_sync(0xffffffffu, r3, k) - gcz;
        float d2  = fmaf(t3, t3, fmaf(t2, t2, t1*t1));
        float gk;
        asm("ex2.approx.f32 %0, %1;" : "=f"(gk) : "f"(d2 * NHL2E));
        unsigned long long gk2;
        asm("mov.b64 %0, {%1, %1};" : "=l"(gk2) : "f"(gk));
        const ulonglong2* am = (const ulonglong2*)(g_amat + (size_t)nbg*DAc);
        ulonglong2 A0 = am[0], A1 = am[1], A2 = am[2];
        FMA2(acc2[0], gk2, A0.x);  FMA2(acc2[1], gk2, A0.y);
        FMA2(acc2[2], gk2, A1.x);  FMA2(acc2[3], gk2, A1.y);
        FMA2(acc2[4], gk2, A2.x);  FMA2(acc2[5], gk2, A2.y);
    }

    float o[12];
#pragma unroll
    for (int p = 0; p < 6; p++)
        asm("mov.b64 {%0, %1}, %2;" : "=f"(o[2*p]), "=f"(o[2*p+1]) : "l"(acc2[p]));
    float4* Mo = (float4*)(g_M + (size_t)warp*MDIM + lane*DAc);
    Mo[0] = make_float4(o[0], o[1], o[2],  o[3]);
    Mo[1] = make_float4(o[4], o[5], o[6],  o[7]);
    Mo[2] = make_float4(o[8], o[9], o[10], o[11]);
}

// ---------------- Fused GEMM (bf16x3): y = (M@Wnem)/K*mask ; af = (y@Wcat)*mask ----------
// (R10 exact version: 128-row tiles, 8 warps 2m x 4n, single-sync double buffer)
#define O_AL 2176
#define O_BH 4352
#define O_BL 6528
#define O_YH 8704
#define O_YL 17408
#define FUSED_SMEM (26112*4)    // 104448 B

__global__ __launch_bounds__(256, 2)
void gemm_fused(const float* __restrict__ A,
                const float* __restrict__ Wn,
                const __nv_bfloat16* __restrict__ Wch,
                const __nv_bfloat16* __restrict__ Wcl,
                const float* __restrict__ maskrow,
                float* __restrict__ AF)
{
    extern __shared__ uint32_t sm[];
#define AH2(b,kp,x) sm[        (b)*1088 + (kp)*136 + (x)]
#define AL2(b,kp,x) sm[O_AL  + (b)*1088 + (kp)*136 + (x)]
#define BH2(b,kp,x) sm[O_BH  + (b)*1088 + (kp)*136 + (x)]
#define BL2(b,kp,x) sm[O_BL  + (b)*1088 + (kp)*136 + (x)]
#define YH(kp,x)    sm[O_YH  + (kp)*136 + (x)]
#define YL(kp,x)    sm[O_YL  + (kp)*136 + (x)]

    int tid  = threadIdx.x;
    int lane = tid & 31;
    int wid  = tid >> 5;
    int warp_m = wid >> 2;
    int warp_n = wid & 3;
    int row0 = blockIdx.x * 128;
    int r4 = lane >> 2, c4 = lane & 3;

    int a_r = tid >> 2;
    int a_c = (tid & 3) * 4;
    int b_c  = tid & 127;
    int b_kg = tid >> 7;

    float4 av0, av1;
    float  bv[8];

    float acc[4][4][4];
#pragma unroll
    for (int i = 0; i < 4; i++)
#pragma unroll
        for (int j = 0; j < 4; j++)
#pragma unroll
            for (int e = 0; e < 4; e++) acc[i][j][e] = 0.0f;

    auto load_regs1 = [&](int kk) {
        av0 = *(const float4*)(A + (size_t)(row0 + a_r)*MDIM + kk + a_c);
        av1 = *(const float4*)(A + (size_t)(row0 + 64 + a_r)*MDIM + kk + a_c);
#pragma unroll
        for (int e = 0; e < 8; e++)
            bv[e] = Wn[(size_t)(kk + b_kg*8 + e)*Fc + b_c];
    };
    auto store_tile1 = [&](int buf) {
        int ac2 = a_c >> 1;
        uint32_t h, l;
        split2(av0.x, av0.y, h, l); AH2(buf, ac2,   a_r)    = h; AL2(buf, ac2,   a_r)    = l;
        split2(av0.z, av0.w, h, l); AH2(buf, ac2+1, a_r)    = h; AL2(buf, ac2+1, a_r)    = l;
        split2(av1.x, av1.y, h, l); AH2(buf, ac2,   a_r+64) = h; AL2(buf, ac2,   a_r+64) = l;
        split2(av1.z, av1.w, h, l); AH2(buf, ac2+1, a_r+64) = h; AL2(buf, ac2+1, a_r+64) = l;
#pragma unroll
        for (int p = 0; p < 4; p++) {
            split2(bv[2*p], bv[2*p+1], h, l);
            BH2(buf, b_kg*4 + p, b_c) = h;
            BL2(buf, b_kg*4 + p, b_c) = l;
        }
    };

    const int T1 = MDIM >> 4;       // 24
    load_regs1(0);
    store_tile1(0);
    __syncthreads();

    for (int t = 0; t < T1; t++) {
        int buf = t & 1;
        if (t + 1 < T1) load_regs1((t + 1) << 4);

        uint32_t bh[4][2], bl[4][2];
#pragma unroll
        for (int j = 0; j < 4; j++) {
            int n = warp_n*32 + j*8 + r4;
            bh[j][0] = BH2(buf, c4,   n);  bh[j][1] = BH2(buf, c4+4, n);
            bl[j][0] = BL2(buf, c4,   n);  bl[j][1] = BL2(buf, c4+4, n);
        }
#pragma unroll
        for (int i = 0; i < 4; i++) {
            int m = warp_m*64 + i*16 + r4;
            uint32_t ah[4], al[4];
            ah[0] = AH2(buf, c4,   m); ah[1] = AH2(buf, c4,   m+8);
            ah[2] = AH2(buf, c4+4, m); ah[3] = AH2(buf, c4+4, m+8);
            al[0] = AL2(buf, c4,   m); al[1] = AL2(buf, c4,   m+8);
            al[2] = AL2(buf, c4+4, m); al[3] = AL2(buf, c4+4, m+8);
#pragma unroll
            for (int j = 0; j < 4; j++) {
                mma_bf16(acc[i][j], ah, bh[j]);
                mma_bf16(acc[i][j], ah, bl[j]);
                mma_bf16(acc[i][j], al, bh[j]);
            }
        }
        if (t + 1 < T1) store_tile1((t + 1) & 1);
        __syncthreads();
    }

    const float inv_k = 1.0f/(float)Kc;
#pragma unroll
    for (int i = 0; i < 4; i++) {
        int rl = warp_m*64 + i*16 + r4;
        float mlo = maskrow[row0 + rl]     * inv_k;
        float mhi = maskrow[row0 + rl + 8] * inv_k;
#pragma unroll
        for (int j = 0; j < 4; j++) {
            int kp = warp_n*16 + j*4 + c4;
            uint32_t h, l;
            split2(acc[i][j][0]*mlo, acc[i][j][1]*mlo, h, l);
            YH(kp, rl) = h;  YL(kp, rl) = l;
            split2(acc[i][j][2]*mhi, acc[i][j][3]*mhi, h, l);
            YH(kp, rl+8) = h;  YL(kp, rl+8) = l;
        }
    }
    __syncthreads();

    uint4 vWh, vWl;
    auto load_regs2 = [&](int kk, int nh) {
        size_t off = (size_t)(nh*128 + b_c)*Fc + kk + b_kg*8;
        vWh = *(const uint4*)(Wch + off);
        vWl = *(const uint4*)(Wcl + off);
    };
    auto store_tile2 = [&](int buf) {
        BH2(buf, b_kg*4+0, b_c) = vWh.x;  BL2(buf, b_kg*4+0, b_c) = vWl.x;
        BH2(buf, b_kg*4+1, b_c) = vWh.y;  BL2(buf, b_kg*4+1, b_c) = vWl.y;
        BH2(buf, b_kg*4+2, b_c) = vWh.z;  BL2(buf, b_kg*4+2, b_c) = vWl.z;
        BH2(buf, b_kg*4+3, b_c) = vWh.w;  BL2(buf, b_kg*4+3, b_c) = vWl.w;
    };

    for (int nh = 0; nh < 2; nh++) {
#pragma unroll
        for (int i = 0; i < 4; i++)
#pragma unroll
            for (int j = 0; j < 4; j++)
#pragma unroll
                for (int e = 0; e < 4; e++) acc[i][j][e] = 0.0f;

        load_regs2(0, nh);
        store_tile2(0);
        __syncthreads();

        const int T2 = Fc >> 4;     // 8
        for (int t = 0; t < T2; t++) {
            int buf = t & 1;
            if (t + 1 < T2) load_regs2((t + 1) << 4, nh);

            uint32_t bh[4][2], bl[4][2];
#pragma unroll
            for (int j = 0; j < 4; j++) {
                int n = warp_n*32 + j*8 + r4;
                bh[j][0] = BH2(buf, c4,   n);  bh[j][1] = BH2(buf, c4+4, n);
                bl[j][0] = BL2(buf, c4,   n);  bl[j][1] = BL2(buf, c4+4, n);
            }
            int kb = t*8;
#pragma unroll
            for (int i = 0; i < 4; i++) {
                int m = warp_m*64 + i*16 + r4;
                uint32_t ah[4], al[4];
                ah[0] = YH(kb + c4,   m); ah[1] = YH(kb + c4,   m+8);
                ah[2] = YH(kb + c4+4, m); ah[3] = YH(kb + c4+4, m+8);
                al[0] = YL(kb + c4,   m); al[1] = YL(kb + c4,   m+8);
                al[2] = YL(kb + c4+4, m); al[3] = YL(kb + c4+4, m+8);
#pragma unroll
                for (int j = 0; j < 4; j++) {
                    mma_bf16(acc[i][j], ah, bh[j]);
                    mma_bf16(acc[i][j], ah, bl[j]);
                    mma_bf16(acc[i][j], al, bh[j]);
                }
            }
            if (t + 1 < T2) store_tile2((t + 1) & 1);
            __syncthreads();
        }

#pragma unroll
        for (int i = 0; i < 4; i++) {
            int rlo = row0 + warp_m*64 + i*16 + r4;
            float mlo = maskrow[rlo];
            float mhi = maskrow[rlo+8];
#pragma unroll
            for (int j = 0; j < 4; j++) {
                int c = nh*128 + warp_n*32 + j*8 + c4*2;
                *(float2*)(AF + (size_t)rlo*(2*Dc) + c)     = make_float2(acc[i][j][0]*mlo, acc[i][j][1]*mlo);
                *(float2*)(AF + (size_t)(rlo+8)*(2*Dc) + c) = make_float2(acc[i][j][2]*mhi, acc[i][j][3]*mhi);
            }
        }
    }
#undef AH2
#undef AL2
#undef BH2
#undef BL2
#undef YH
#undef YL
}

// ---------------- K4: warp-per-AA masked softmax pooling (float4 per lane) ----------------
__global__ void k4_pool(const int*  __restrict__ aa_nb_idx,
                        const int*  __restrict__ seq_idx_atom,
                        const int*  __restrict__ seq_idx_aa,
                        const float* __restrict__ mask_aa)
{
    int w    = threadIdx.x >> 5;
    int lane = threadIdx.x & 31;
    int bm   = blockIdx.x * 4 + w;          // 0..NAAT-1
    int b    = bm / NAAc;

    // lanes 0..13 gather neighbor metadata; broadcast to all lanes via shfl
    int   ag_l = 0;
    float mk_l = 0.0f, gm_l = 0.0f;
    if (lane < KNCc) {
        int nb = aa_nb_idx[(size_t)bm*KNCc + lane];
        ag_l = b*NAc + nb;
        mk_l = g_masky[ag_l];
        int sq = seq_idx_atom[ag_l];
        gm_l = (sq == seq_idx_aa[bm]) ? mk_l : 0.0f;
    }
    int   ag[KNCc];
    float mk[KNCc], gm[KNCc];
#pragma unroll
    for (int k = 0; k < KNCc; k++) {
        ag[k] = __shfl_sync(0xffffffffu, ag_l, k);
        mk[k] = __shfl_sync(0xffffffffu, mk_l, k);
        gm[k] = __shfl_sync(0xffffffffu, gm_l, k);
    }

    // each lane owns 4 feature columns: d = lane*4 .. lane*4+3
    float4 att[KNCc];
#pragma unroll
    for (int k = 0; k < KNCc; k++)
        att[k] = *(const float4*)(g_af + (size_t)ag[k]*(2*Dc) + lane*4);

    float4 mx = make_float4(-3.0e38f, -3.0e38f, -3.0e38f, -3.0e38f);
#pragma unroll
    for (int k = 0; k < KNCc; k++) {
        bool pos = (mk[k] > 0.0f);
        att[k].x = pos ? att[k].x : -1.0e9f;
        att[k].y = pos ? att[k].y : -1.0e9f;
        att[k].z = pos ? att[k].z : -1.0e9f;
        att[k].w = pos ? att[k].w : -1.0e9f;
        mx.x = fmaxf(mx.x, att[k].x);
        mx.y = fmaxf(mx.y, att[k].y);
        mx.z = fmaxf(mx.z, att[k].z);
        mx.w = fmaxf(mx.w, att[k].w);
    }
    float4 se = make_float4(0.f, 0.f, 0.f, 0.f);
#pragma unroll
    for (int k = 0; k < KNCc; k++) {
        att[k].x = __expf(att[k].x - mx.x);
        att[k].y = __expf(att[k].y - mx.y);
        att[k].z = __expf(att[k].z - mx.z);
        att[k].w = __expf(att[k].w - mx.w);
        se.x += att[k].x;  se.y += att[k].y;
        se.z += att[k].z;  se.w += att[k].w;
    }
    float4 ise = make_float4(1.f/se.x, 1.f/se.y, 1.f/se.z, 1.f/se.w);
    float4 sw = make_float4(0.f, 0.f, 0.f, 0.f);
#pragma unroll
    for (int k = 0; k < KNCc; k++) {
        att[k].x = att[k].x*ise.x*gm[k];  sw.x += att[k].x;
        att[k].y = att[k].y*ise.y*gm[k];  sw.y += att[k].y;
        att[k].z = att[k].z*ise.z*gm[k];  sw.z += att[k].z;
        att[k].w = att[k].w*ise.w*gm[k];  sw.w += att[k].w;
    }
    float4 idn = make_float4(1.f/(sw.x+1e-8f), 1.f/(sw.y+1e-8f),
                             1.f/(sw.z+1e-8f), 1.f/(sw.w+1e-8f));
    float4 pooled = make_float4(0.f, 0.f, 0.f, 0.f);
#pragma unroll
    for (int k = 0; k < KNCc; k++) {
        float4 ft = *(const float4*)(g_af + (size_t)ag[k]*(2*Dc) + Dc + lane*4);
        pooled.x += att[k].x*idn.x*ft.x;
        pooled.y += att[k].y*idn.y*ft.y;
        pooled.z += att[k].z*idn.z*ft.z;
        pooled.w += att[k].w*idn.w*ft.w;
    }
    float ma = mask_aa[bm];
    pooled.x *= ma;  pooled.y *= ma;  pooled.z *= ma;  pooled.w *= ma;
    *(float4*)(g_pooled + (size_t)bm*Dc + lane*4) = pooled;
}

// ---------------- K5a: partial batch-norm sums (coalesced, 64 blocks x 128 rows) ----------
__global__ void k5a(const float* __restrict__ mask_aa)
{
    int d  = threadIdx.x;           // 0..127
    int r0 = blockIdx.x * 128;      // 64 blocks
    float s0 = 0.0f, s1 = 0.0f, s2 = 0.0f;
    for (int r = r0; r < r0 + 128; r++) {
        float m = mask_aa[r];
        float p = g_pooled[(size_t)r*Dc + d];
        s0 += m;
        s1 += m*p;
        s2 += m*p*p;
    }
    g_part[(blockIdx.x*3 + 0)*Dc + d] = s0;
    g_part[(blockIdx.x*3 + 1)*Dc + d] = s1;
    g_part[(blockIdx.x*3 + 2)*Dc + d] = s2;
}

// ---------------- K5b: combine partials -> mean, inv-std ----------------
__global__ void k5b()
{
    int d = threadIdx.x;            // 128 threads
    float s0 = 0.0f, s1 = 0.0f, s2 = 0.0f;
    for (int i = 0; i < 64; i++) {
        s0 += g_part[(i*3 + 0)*Dc + d];
        s1 += g_part[(i*3 + 1)*Dc + d];
        s2 += g_part[(i*3 + 2)*Dc + d];
    }
    float n = s0 + 1e-8f;
    float mean = s1/n;
    float var = (s2 - 2.0f*mean*s1 + mean*mean*s0)/n;
    g_mean[d] = mean;
    g_inv[d]  = rsqrtf(var + 1e-5f);
}

// ---------------- K6: normalize + relu + write outputs ----------------
__global__ void k6_out(const float* __restrict__ gamma,
                       const float* __restrict__ beta,
                       const float* __restrict__ mask_aa,
                       float* __restrict__ out, int out_size)
{
    int idx = blockIdx.x * blockDim.x + threadIdx.x;
    const int total = NAAT*Dc;
    if (idx < total) {
        int d = idx & (Dc-1);
        int r = idx >> 7;
        float p = g_pooled[idx];
        float v = (gamma[d]*(p - g_mean[d])*g_inv[d] + beta[d]) * mask_aa[r];
        out[idx] = fmaxf(v, 0.0f);
    }
    if (idx < NAAT && total + idx < out_size) {
        out[total + idx] = mask_aa[idx];
    }
}

// ---------------- launch ----------------
extern "C" void kernel_launch(void* const* d_in, const int* in_sizes, int n_in,
                              void* d_out, int out_size)
{
    const float* point_clouds  = (const float*)d_in[0];
    const float* mask_atom     = (const float*)d_in[1];
    const float* mask_aa       = (const float*)d_in[2];
    const float* attr_table    = (const float*)d_in[3];
    const float* gauss_centers = (const float*)d_in[4];
    const float* W_nem         = (const float*)d_in[5];
    const float* W_att         = (const float*)d_in[6];
    const float* W_feat        = (const float*)d_in[7];
    const float* bn_gamma      = (const float*)d_in[8];
    const float* bn_beta       = (const float*)d_in[9];
    const int*   frame_idx     = (const int*)d_in[10];
    const int*   attr_idx      = (const int*)d_in[11];
    const int*   nb_idx        = (const int*)d_in[12];
    const int*   seq_idx_atom  = (const int*)d_in[13];
    const int*   seq_idx_aa    = (const int*)d_in[14];
    const int*   aa_nb_idx     = (const int*)d_in[15];
    float* out = (float*)d_out;

    float *pM, *pAF, *pMask;
    __nv_bfloat16 *pWch, *pWcl;
    cudaGetSymbolAddress((void**)&pM,   g_M);
    cudaGetSymbolAddress((void**)&pAF,  g_af);
    cudaGetSymbolAddress((void**)&pMask, g_masky);
    cudaGetSymbolAddress((void**)&pWch, g_Wch);
    cudaGetSymbolAddress((void**)&pWcl, g_Wcl);

    cudaFuncSetAttribute(gemm_fused, cudaFuncAttributeMaxDynamicSharedMemorySize, FUSED_SMEM);

    // K0 + Wcat prep (merged)
    k0w<<<(NATOM + 2*Dc*Fc + 255)/256, 256>>>(point_clouds, mask_atom, attr_table,
                                              frame_idx, attr_idx, W_att, W_feat);

    // K1: build M
    k1_buildM<<<(NATOM*32)/256, 256>>>(point_clouds, frame_idx, nb_idx, gauss_centers);

    // Fused GEMM1+GEMM2 (R10 config: 128-row tiles)
    gemm_fused<<<NATOM/128, 256, FUSED_SMEM>>>(pM, W_nem, pWch, pWcl, pMask, pAF);

    // K4: warp-per-AA pooling
    k4_pool<<<NAAT/4, 128>>>(aa_nb_idx, seq_idx_atom, seq_idx_aa, mask_aa);

    // K5: batch-norm stats (two-stage, coalesced)
    k5a<<<64, 128>>>(mask_aa);
    k5b<<<1, 128>>>();

    // K6: outputs
    k6_out<<<(NAAT*Dc + 255)/256, 256>>>(bn_gamma, bn_beta, mask_aa, out, out_size);
}